// round 2
// baseline (speedup 1.0000x reference)
#include <cuda_runtime.h>

typedef unsigned long long u64;

#define TT 50
#define EE 10

__device__ __forceinline__ u64 ffma2(u64 a, u64 b, u64 c){
    u64 d; asm("fma.rn.f32x2 %0, %1, %2, %3;" : "=l"(d) : "l"(a), "l"(b), "l"(c)); return d;
}
__device__ __forceinline__ u64 splat2(float v){
    u64 r; asm("mov.b64 %0, {%1, %1};" : "=l"(r) : "f"(v)); return r;
}
__device__ __forceinline__ void unpack2(u64 v, float& lo, float& hi){
    asm("mov.b64 {%0, %1}, %2;" : "=f"(lo), "=f"(hi) : "l"(v));
}
__device__ __forceinline__ float sigmoidf_fast(float v){
    return __fdividef(1.0f, 1.0f + __expf(-v));
}
__device__ __forceinline__ float tanhf_fast(float v){
    return 1.0f - __fdividef(2.0f, __expf(2.0f * v) + 1.0f);
}

__device__ __forceinline__ void mac_row(u64 acc[5], const float* __restrict__ row, u64 s){
    const ulonglong2* p = (const ulonglong2*)row;   // 16B-aligned (rows padded to 16 floats)
    ulonglong2 w01 = p[0];
    ulonglong2 w23 = p[1];
    u64 w4 = *(const u64*)(row + 8);
    acc[0] = ffma2(s, w01.x, acc[0]);
    acc[1] = ffma2(s, w01.y, acc[1]);
    acc[2] = ffma2(s, w23.x, acc[2]);
    acc[3] = ffma2(s, w23.y, acc[3]);
    acc[4] = ffma2(s, w4,    acc[4]);
}

__global__ void __launch_bounds__(128) augru_kernel(
    const float* __restrict__ X, const float* __restrict__ Aat,
    const float* __restrict__ h0,
    const float* __restrict__ Wi_r, const float* __restrict__ bi_r,
    const float* __restrict__ Wh_r, const float* __restrict__ Ws_r, const float* __restrict__ bs_r,
    const float* __restrict__ Wi_z, const float* __restrict__ bi_z,
    const float* __restrict__ Wh_z, const float* __restrict__ Ws_z, const float* __restrict__ bs_z,
    const float* __restrict__ Wi_h, const float* __restrict__ bi_h,
    const float* __restrict__ Wh_h, const float* __restrict__ Wt_h, const float* __restrict__ bt_h,
    float* __restrict__ out)
{
    // Fused: sW[0]=Wi_r@Ws_r, sW[1]=Wh_r@Ws_r, sW[2]=Wi_z@Ws_z,
    //        sW[3]=Wh_z@Ws_z, sW[4]=Wi_h@Wt_h, sW[5]=Wh_h@Wt_h. Rows padded to 16.
    __shared__ __align__(16) float sW[6][160];
    __shared__ __align__(16) float sB[3][16];
    __shared__ float sH0[16];

    {
        const float* W1[6] = {Wi_r, Wh_r, Wi_z, Wh_z, Wi_h, Wh_h};
        const float* W2[6] = {Ws_r, Ws_r, Ws_z, Ws_z, Wt_h, Wt_h};
        for (int idx = threadIdx.x; idx < 6 * 160; idx += blockDim.x){
            int m = idx / 160, r = idx % 160, i = r >> 4, j = r & 15;
            float v = 0.0f;
            if (j < EE){
                const float* a = W1[m]; const float* b2 = W2[m];
                #pragma unroll
                for (int k = 0; k < EE; k++) v = fmaf(a[i*EE + k], b2[k*EE + j], v);
            }
            sW[m][r] = v;
        }
        for (int idx = threadIdx.x; idx < 48; idx += blockDim.x){
            int g = idx >> 4, j = idx & 15;
            float v = 0.0f;
            if (j < EE){
                const float* bi = (g==0) ? bi_r : (g==1) ? bi_z : bi_h;
                const float* bs = (g==0) ? bs_r : (g==1) ? bs_z : bt_h;
                const float* Wg = (g==0) ? Ws_r : (g==1) ? Ws_z : Wt_h;
                v = bs[j];
                #pragma unroll
                for (int k = 0; k < EE; k++) v = fmaf(bi[k], Wg[k*EE + j], v);
            }
            sB[g][j] = v;
        }
        if (threadIdx.x < 16) sH0[threadIdx.x] = (threadIdx.x < EE) ? h0[threadIdx.x] : 0.0f;
    }
    __syncthreads();

    long b = (long)blockIdx.x * blockDim.x + threadIdx.x;
    // Per-batch row is 500 floats = 2000 B, 16B-aligned. Chunk c covers t=2c,2c+1:
    // 80 B = 5 float4, offset 80*c from row base -> every chunk 16B-aligned.
    const float4* xp4 = (const float4*)(X   + b * (TT * EE));
    const float4* ap4 = (const float4*)(Aat + b * (TT * EE));

    float h[EE];
    #pragma unroll
    for (int j = 0; j < EE; j++) h[j] = sH0[j];

    #pragma unroll 1
    for (int c = 0; c < TT/2; c++){
        // Batched wide loads: 10 independent LDG.128 (MLP=10), full sector use.
        float4 xq[5], aq[5];
        #pragma unroll
        for (int p = 0; p < 5; p++){ xq[p] = xp4[5*c + p]; }
        #pragma unroll
        for (int p = 0; p < 5; p++){ aq[p] = ap4[5*c + p]; }

        float xs[20], av[20];
        #pragma unroll
        for (int p = 0; p < 5; p++){
            xs[4*p+0] = xq[p].x; xs[4*p+1] = xq[p].y; xs[4*p+2] = xq[p].z; xs[4*p+3] = xq[p].w;
            av[4*p+0] = aq[p].x; av[4*p+1] = aq[p].y; av[4*p+2] = aq[p].z; av[4*p+3] = aq[p].w;
        }

        #pragma unroll
        for (int half = 0; half < 2; half++){
            const float* x = xs + 10*half;
            const float* a = av + 10*half;

            u64 accR[5], accZ[5], accH[5];
            #pragma unroll
            for (int p = 0; p < 5; p++){
                accR[p] = *(const u64*)&sB[0][2*p];
                accZ[p] = *(const u64*)&sB[1][2*p];
                accH[p] = *(const u64*)&sB[2][2*p];
            }

            // x contributions to all three gates
            #pragma unroll
            for (int i = 0; i < EE; i++){
                u64 sx = splat2(x[i]);
                mac_row(accR, &sW[0][i*16], sx);
                mac_row(accZ, &sW[2][i*16], sx);
                mac_row(accH, &sW[4][i*16], sx);
            }
            // h contributions to r and z
            #pragma unroll
            for (int i = 0; i < EE; i++){
                u64 sh = splat2(h[i]);
                mac_row(accR, &sW[1][i*16], sh);
                mac_row(accZ, &sW[3][i*16], sh);
            }

            float r[EE], g[EE];
            #pragma unroll
            for (int p = 0; p < 5; p++){
                float a0, a1; unpack2(accR[p], a0, a1);
                r[2*p]   = sigmoidf_fast(a0);
                r[2*p+1] = sigmoidf_fast(a1);
                float z0, z1; unpack2(accZ[p], z0, z1);
                g[2*p]   = h[2*p]   * sigmoidf_fast(z0);
                g[2*p+1] = h[2*p+1] * sigmoidf_fast(z1);
            }

            // (h*z) contribution to candidate
            #pragma unroll
            for (int i = 0; i < EE; i++){
                u64 sg = splat2(g[i]);
                mac_row(accH, &sW[5][i*16], sg);
            }

            // hc = tanh(...); Ra = a*r; h = h + Ra*(hc - h)
            #pragma unroll
            for (int p = 0; p < 5; p++){
                float c0, c1; unpack2(accH[p], c0, c1);
                float hc0 = tanhf_fast(c0);
                float hc1 = tanhf_fast(c1);
                float Ra0 = a[2*p]   * r[2*p];
                float Ra1 = a[2*p+1] * r[2*p+1];
                h[2*p]   = h[2*p]   + Ra0 * (hc0 - h[2*p]);
                h[2*p+1] = h[2*p+1] + Ra1 * (hc1 - h[2*p+1]);
            }
        }
    }

    #pragma unroll
    for (int p = 0; p < 5; p++){
        float2 o; o.x = h[2*p]; o.y = h[2*p+1];
        *(float2*)(out + b*EE + 2*p) = o;
    }
}

extern "C" void kernel_launch(void* const* d_in, const int* in_sizes, int n_in,
                              void* d_out, int out_size)
{
    const float* X   = (const float*)d_in[0];
    const float* Aat = (const float*)d_in[1];
    const float* h0  = (const float*)d_in[2];
    int Bn = in_sizes[0] / (TT * EE);   // 65536
    int threads = 128;
    int blocks = Bn / threads;          // 512
    augru_kernel<<<blocks, threads>>>(
        X, Aat, h0,
        (const float*)d_in[3],  (const float*)d_in[4],  (const float*)d_in[5],
        (const float*)d_in[6],  (const float*)d_in[7],
        (const float*)d_in[8],  (const float*)d_in[9],  (const float*)d_in[10],
        (const float*)d_in[11], (const float*)d_in[12],
        (const float*)d_in[13], (const float*)d_in[14], (const float*)d_in[15],
        (const float*)d_in[16], (const float*)d_in[17],
        (float*)d_out);
}

// round 3
// speedup vs baseline: 1.0541x; 1.0541x over previous
#include <cuda_runtime.h>

typedef unsigned long long u64;

#define TT 50
#define EE 10
#define BB 65536

// Scratch: S[t][b][20] = { x_t[b][0..10), a_t[b][0..10) }, 262 MB device global.
__device__ float g_S[(long)TT * BB * 20];

// ---------------- Pass 1: transpose [B][T][E] -> [T][B][20] ----------------
#define BTILE 32
#define TCH   10

__global__ void __launch_bounds__(256) transpose_kernel(
    const float* __restrict__ X, const float* __restrict__ A)
{
    __shared__ __align__(16) float sX[BTILE][TCH * EE];   // 32 x 100
    __shared__ __align__(16) float sA[BTILE][TCH * EE];

    int b0 = blockIdx.x * BTILE;
    int tcy = blockIdx.y;              // t chunk index, t0 = tcy*TCH
    // Per row segment: floats [tcy*100, tcy*100+100) of the 500-float row -> 25 float4
    const float4* X4 = (const float4*)X;
    const float4* A4 = (const float4*)A;

    for (int idx = threadIdx.x; idx < BTILE * 25; idx += blockDim.x){
        int r = idx / 25, c = idx % 25;
        long g = (long)(b0 + r) * 125 + (long)tcy * 25 + c;
        float4 v = X4[g];
        *(float4*)&sX[r][4*c] = v;
        float4 w = A4[g];
        *(float4*)&sA[r][4*c] = w;
    }
    __syncthreads();

    // Store: S[(t0+t)*B + (b0+b)][e], e in [0,20): first 10 from X, next 10 from A.
    // float2 granularity: e2 in [0,10): e2<5 -> X pair e2, else A pair e2-5.
    float2* S2 = (float2*)g_S;
    for (int idx = threadIdx.x; idx < TCH * BTILE * 10; idx += blockDim.x){
        int e2 = idx % 10;
        int b  = (idx / 10) % BTILE;
        int t  = idx / (10 * BTILE);
        float2 v;
        if (e2 < 5) v = *(const float2*)&sX[b][t*EE + 2*e2];
        else        v = *(const float2*)&sA[b][t*EE + 2*(e2-5)];
        long o = ((long)(tcy*TCH + t) * BB + (b0 + b)) * 10 + e2;
        S2[o] = v;
    }
}

// ---------------- Pass 2: recurrence over [T][B][20] ----------------
__device__ __forceinline__ u64 ffma2(u64 a, u64 b, u64 c){
    u64 d; asm("fma.rn.f32x2 %0, %1, %2, %3;" : "=l"(d) : "l"(a), "l"(b), "l"(c)); return d;
}
__device__ __forceinline__ u64 splat2(float v){
    u64 r; asm("mov.b64 %0, {%1, %1};" : "=l"(r) : "f"(v)); return r;
}
__device__ __forceinline__ void unpack2(u64 v, float& lo, float& hi){
    asm("mov.b64 {%0, %1}, %2;" : "=f"(lo), "=f"(hi) : "l"(v));
}
__device__ __forceinline__ float sigmoidf_fast(float v){
    return __fdividef(1.0f, 1.0f + __expf(-v));
}
__device__ __forceinline__ float tanhf_fast(float v){
    return 1.0f - __fdividef(2.0f, __expf(2.0f * v) + 1.0f);
}

__device__ __forceinline__ void mac_row(u64 acc[5], const float* __restrict__ row, u64 s){
    const ulonglong2* p = (const ulonglong2*)row;
    ulonglong2 w01 = p[0];
    ulonglong2 w23 = p[1];
    u64 w4 = *(const u64*)(row + 8);
    acc[0] = ffma2(s, w01.x, acc[0]);
    acc[1] = ffma2(s, w01.y, acc[1]);
    acc[2] = ffma2(s, w23.x, acc[2]);
    acc[3] = ffma2(s, w23.y, acc[3]);
    acc[4] = ffma2(s, w4,    acc[4]);
}

__global__ void __launch_bounds__(256) augru_kernel(
    const float* __restrict__ h0,
    const float* __restrict__ Wi_r, const float* __restrict__ bi_r,
    const float* __restrict__ Wh_r, const float* __restrict__ Ws_r, const float* __restrict__ bs_r,
    const float* __restrict__ Wi_z, const float* __restrict__ bi_z,
    const float* __restrict__ Wh_z, const float* __restrict__ Ws_z, const float* __restrict__ bs_z,
    const float* __restrict__ Wi_h, const float* __restrict__ bi_h,
    const float* __restrict__ Wh_h, const float* __restrict__ Wt_h, const float* __restrict__ bt_h,
    float* __restrict__ out)
{
    // Fused: sW[0]=Wi_r@Ws_r, sW[1]=Wh_r@Ws_r, sW[2]=Wi_z@Ws_z,
    //        sW[3]=Wh_z@Ws_z, sW[4]=Wi_h@Wt_h, sW[5]=Wh_h@Wt_h. Rows padded to 16.
    __shared__ __align__(16) float sW[6][160];
    __shared__ __align__(16) float sB[3][16];
    __shared__ float sH0[16];

    {
        const float* W1[6] = {Wi_r, Wh_r, Wi_z, Wh_z, Wi_h, Wh_h};
        const float* W2[6] = {Ws_r, Ws_r, Ws_z, Ws_z, Wt_h, Wt_h};
        for (int idx = threadIdx.x; idx < 6 * 160; idx += blockDim.x){
            int m = idx / 160, r = idx % 160, i = r >> 4, j = r & 15;
            float v = 0.0f;
            if (j < EE){
                const float* a = W1[m]; const float* b2 = W2[m];
                #pragma unroll
                for (int k = 0; k < EE; k++) v = fmaf(a[i*EE + k], b2[k*EE + j], v);
            }
            sW[m][r] = v;
        }
        for (int idx = threadIdx.x; idx < 48; idx += blockDim.x){
            int g = idx >> 4, j = idx & 15;
            float v = 0.0f;
            if (j < EE){
                const float* bi = (g==0) ? bi_r : (g==1) ? bi_z : bi_h;
                const float* bs = (g==0) ? bs_r : (g==1) ? bs_z : bt_h;
                const float* Wg = (g==0) ? Ws_r : (g==1) ? Ws_z : Wt_h;
                v = bs[j];
                #pragma unroll
                for (int k = 0; k < EE; k++) v = fmaf(bi[k], Wg[k*EE + j], v);
            }
            sB[g][j] = v;
        }
        if (threadIdx.x < 16) sH0[threadIdx.x] = (threadIdx.x < EE) ? h0[threadIdx.x] : 0.0f;
    }
    __syncthreads();

    long b = (long)blockIdx.x * blockDim.x + threadIdx.x;
    // Per-step block for this thread: 20 floats (80 B), 16B-aligned; step stride B*20 floats.
    const float4* Sp = (const float4*)(g_S + b * 20);

    float h[EE];
    #pragma unroll
    for (int j = 0; j < EE; j++) h[j] = sH0[j];

    float4 q[5];
    #pragma unroll
    for (int p = 0; p < 5; p++) q[p] = Sp[p];   // t = 0

    #pragma unroll 1
    for (int t = 0; t < TT; t++){
        // prefetch t+1 (dense, lane-contiguous)
        int tn = (t + 1 < TT) ? (t + 1) : t;
        float4 qn[5];
        #pragma unroll
        for (int p = 0; p < 5; p++) qn[p] = Sp[(long)tn * (BB * 5) + p];

        float x[EE], a[EE];
        x[0]=q[0].x; x[1]=q[0].y; x[2]=q[0].z; x[3]=q[0].w;
        x[4]=q[1].x; x[5]=q[1].y; x[6]=q[1].z; x[7]=q[1].w;
        x[8]=q[2].x; x[9]=q[2].y;
        a[0]=q[2].z; a[1]=q[2].w;
        a[2]=q[3].x; a[3]=q[3].y; a[4]=q[3].z; a[5]=q[3].w;
        a[6]=q[4].x; a[7]=q[4].y; a[8]=q[4].z; a[9]=q[4].w;

        u64 accR[5], accZ[5], accH[5];
        #pragma unroll
        for (int p = 0; p < 5; p++){
            accR[p] = *(const u64*)&sB[0][2*p];
            accZ[p] = *(const u64*)&sB[1][2*p];
            accH[p] = *(const u64*)&sB[2][2*p];
        }

        #pragma unroll
        for (int i = 0; i < EE; i++){
            u64 sx = splat2(x[i]);
            mac_row(accR, &sW[0][i*16], sx);
            mac_row(accZ, &sW[2][i*16], sx);
            mac_row(accH, &sW[4][i*16], sx);
        }
        #pragma unroll
        for (int i = 0; i < EE; i++){
            u64 sh = splat2(h[i]);
            mac_row(accR, &sW[1][i*16], sh);
            mac_row(accZ, &sW[3][i*16], sh);
        }

        float r[EE], g[EE];
        #pragma unroll
        for (int p = 0; p < 5; p++){
            float r0, r1; unpack2(accR[p], r0, r1);
            r[2*p]   = sigmoidf_fast(r0);
            r[2*p+1] = sigmoidf_fast(r1);
            float z0, z1; unpack2(accZ[p], z0, z1);
            g[2*p]   = h[2*p]   * sigmoidf_fast(z0);
            g[2*p+1] = h[2*p+1] * sigmoidf_fast(z1);
        }

        #pragma unroll
        for (int i = 0; i < EE; i++){
            u64 sg = splat2(g[i]);
            mac_row(accH, &sW[5][i*16], sg);
        }

        #pragma unroll
        for (int p = 0; p < 5; p++){
            float c0, c1; unpack2(accH[p], c0, c1);
            float hc0 = tanhf_fast(c0);
            float hc1 = tanhf_fast(c1);
            float Ra0 = a[2*p]   * r[2*p];
            float Ra1 = a[2*p+1] * r[2*p+1];
            h[2*p]   = h[2*p]   + Ra0 * (hc0 - h[2*p]);
            h[2*p+1] = h[2*p+1] + Ra1 * (hc1 - h[2*p+1]);
        }

        #pragma unroll
        for (int p = 0; p < 5; p++) q[p] = qn[p];
    }

    #pragma unroll
    for (int p = 0; p < 5; p++){
        float2 o; o.x = h[2*p]; o.y = h[2*p+1];
        *(float2*)(out + b*EE + 2*p) = o;
    }
}

extern "C" void kernel_launch(void* const* d_in, const int* in_sizes, int n_in,
                              void* d_out, int out_size)
{
    const float* X   = (const float*)d_in[0];
    const float* Aat = (const float*)d_in[1];
    const float* h0  = (const float*)d_in[2];

    dim3 tg(BB / BTILE, TT / TCH);      // 2048 x 5
    transpose_kernel<<<tg, 256>>>(X, Aat);

    int threads = 256;
    int blocks = BB / threads;          // 256
    augru_kernel<<<blocks, threads>>>(
        h0,
        (const float*)d_in[3],  (const float*)d_in[4],  (const float*)d_in[5],
        (const float*)d_in[6],  (const float*)d_in[7],
        (const float*)d_in[8],  (const float*)d_in[9],  (const float*)d_in[10],
        (const float*)d_in[11], (const float*)d_in[12],
        (const float*)d_in[13], (const float*)d_in[14], (const float*)d_in[15],
        (const float*)d_in[16], (const float*)d_in[17],
        (float*)d_out);
}

// round 4
// speedup vs baseline: 4.3156x; 4.0941x over previous
#include <cuda_runtime.h>

#define TT 50
#define EE 10
#define BB 65536

// Scratch: S[t][b][20] = { x_t[b][0..10), a_t[b][0..10) }, 262 MB device global.
__device__ float g_S[(long)TT * BB * 20];

// ---------------- Pass 1: transpose [B][T][E] -> [T][B][20] ----------------
#define BTILE 32
#define TCH   10

__global__ void __launch_bounds__(256) transpose_kernel(
    const float* __restrict__ X, const float* __restrict__ A)
{
    __shared__ __align__(16) float sX[BTILE][TCH * EE];   // 32 x 100
    __shared__ __align__(16) float sA[BTILE][TCH * EE];

    int b0 = blockIdx.x * BTILE;
    int tcy = blockIdx.y;
    const float4* X4 = (const float4*)X;
    const float4* A4 = (const float4*)A;

    for (int idx = threadIdx.x; idx < BTILE * 25; idx += blockDim.x){
        int r = idx / 25, c = idx % 25;
        long g = (long)(b0 + r) * 125 + (long)tcy * 25 + c;
        float4 v = X4[g];
        *(float4*)&sX[r][4*c] = v;
        float4 w = A4[g];
        *(float4*)&sA[r][4*c] = w;
    }
    __syncthreads();

    float2* S2 = (float2*)g_S;
    for (int idx = threadIdx.x; idx < TCH * BTILE * 10; idx += blockDim.x){
        int e2 = idx % 10;
        int b  = (idx / 10) % BTILE;
        int t  = idx / (10 * BTILE);
        float2 v;
        if (e2 < 5) v = *(const float2*)&sX[b][t*EE + 2*e2];
        else        v = *(const float2*)&sA[b][t*EE + 2*(e2-5)];
        long o = ((long)(tcy*TCH + t) * BB + (b0 + b)) * 10 + e2;
        S2[o] = v;
    }
}

// ---------------- Pass 2: recurrence, inputs staged via shared memory ----------------
__device__ __forceinline__ float sigmoidf_fast(float v){
    return __fdividef(1.0f, 1.0f + __expf(-v));
}
__device__ __forceinline__ float tanhf_fast(float v){
    return 1.0f - __fdividef(2.0f, __expf(2.0f * v) + 1.0f);
}

#define NTH 256
#define RSTRIDE 22   // floats per thread-row in the staging buffer (even, coprime*: conflict-free LDS.64)

__global__ void __launch_bounds__(NTH) augru_kernel(
    const float* __restrict__ h0,
    const float* __restrict__ Wi_r, const float* __restrict__ bi_r,
    const float* __restrict__ Wh_r, const float* __restrict__ Ws_r, const float* __restrict__ bs_r,
    const float* __restrict__ Wi_z, const float* __restrict__ bi_z,
    const float* __restrict__ Wh_z, const float* __restrict__ Ws_z, const float* __restrict__ bs_z,
    const float* __restrict__ Wi_h, const float* __restrict__ bi_h,
    const float* __restrict__ Wh_h, const float* __restrict__ Wt_h, const float* __restrict__ bt_h,
    float* __restrict__ out)
{
    // Fused weights: W0=Wi_r@Ws_r, W1=Wh_r@Ws_r, W2=Wi_z@Ws_z, W3=Wh_z@Ws_z,
    //                W4=Wi_h@Wt_h, W5=Wh_h@Wt_h  (rows padded to 12 floats)
    __shared__ float sW[6][EE][12];
    __shared__ float sBias[3][12];
    __shared__ float sH0[12];
    __shared__ float sIn[2][NTH * RSTRIDE];   // double-buffered per-step slab: 2 x 22528 B

    {
        const float* W1[6] = {Wi_r, Wh_r, Wi_z, Wh_z, Wi_h, Wh_h};
        const float* W2[6] = {Ws_r, Ws_r, Ws_z, Ws_z, Wt_h, Wt_h};
        for (int idx = threadIdx.x; idx < 6 * EE * 12; idx += blockDim.x){
            int m = idx / (EE*12), r = idx % (EE*12), i = r / 12, j = r % 12;
            float v = 0.0f;
            if (j < EE){
                const float* a = W1[m]; const float* b2 = W2[m];
                #pragma unroll
                for (int k = 0; k < EE; k++) v = fmaf(a[i*EE + k], b2[k*EE + j], v);
            }
            sW[m][i][j] = v;
        }
        for (int idx = threadIdx.x; idx < 36; idx += blockDim.x){
            int g = idx / 12, j = idx % 12;
            float v = 0.0f;
            if (j < EE){
                const float* bi = (g==0) ? bi_r : (g==1) ? bi_z : bi_h;
                const float* bs = (g==0) ? bs_r : (g==1) ? bs_z : bt_h;
                const float* Wg = (g==0) ? Ws_r : (g==1) ? Ws_z : Wt_h;
                v = bs[j];
                #pragma unroll
                for (int k = 0; k < EE; k++) v = fmaf(bi[k], Wg[k*EE + j], v);
            }
            sBias[g][j] = v;
        }
        if (threadIdx.x < 12) sH0[threadIdx.x] = (threadIdx.x < EE) ? h0[threadIdx.x] : 0.0f;
    }

    const int tid = threadIdx.x;
    const int b0  = blockIdx.x * NTH;

    // Cooperative load of step-t slab: 256 batches x 20 floats = 1280 float4, coalesced.
    // Each thread owns float4 indices tid + 256*k, k=0..4.
    const float4* Sbase = (const float4*)(g_S + (long)b0 * 20);

    float4 f4[5];
    #pragma unroll
    for (int k = 0; k < 5; k++) f4[k] = Sbase[tid + NTH*k];   // t = 0

    // STS: element e = 4*(tid+256k); row = e/20, col = e%20 (col multiple of 4)
    #pragma unroll
    for (int k = 0; k < 5; k++){
        int e = 4*(tid + NTH*k);
        int row = e / 20, col = e % 20;
        float* d = &sIn[0][row * RSTRIDE + col];
        *(float2*)(d)     = make_float2(f4[k].x, f4[k].y);
        *(float2*)(d + 2) = make_float2(f4[k].z, f4[k].w);
    }
    __syncthreads();

    float h[EE];
    #pragma unroll
    for (int j = 0; j < EE; j++) h[j] = sH0[j];

    #pragma unroll 1
    for (int t = 0; t < TT; t++){
        // issue global loads for step t+1 (consumed at end of iteration)
        if (t + 1 < TT){
            const float4* Sn = (const float4*)(g_S + ((long)(t+1) * BB + b0) * 20);
            #pragma unroll
            for (int k = 0; k < 5; k++) f4[k] = Sn[tid + NTH*k];
        }

        // ---- compute step t from sIn[t&1] ----
        const float* my = &sIn[t & 1][tid * RSTRIDE];
        float x[EE], a[EE];
        #pragma unroll
        for (int p = 0; p < 5; p++){
            float2 v = *(const float2*)(my + 2*p);
            x[2*p] = v.x; x[2*p+1] = v.y;
            float2 w = *(const float2*)(my + 10 + 2*p);
            a[2*p] = w.x; a[2*p+1] = w.y;
        }

        float accR[EE], accZ[EE], accH[EE];
        #pragma unroll
        for (int j = 0; j < EE; j++){
            accR[j] = sBias[0][j];
            accZ[j] = sBias[1][j];
            accH[j] = sBias[2][j];
        }

        #pragma unroll
        for (int i = 0; i < EE; i++){
            float xi = x[i];
            #pragma unroll
            for (int j = 0; j < EE; j++){
                accR[j] = fmaf(xi, sW[0][i][j], accR[j]);
                accZ[j] = fmaf(xi, sW[2][i][j], accZ[j]);
                accH[j] = fmaf(xi, sW[4][i][j], accH[j]);
            }
        }
        #pragma unroll
        for (int i = 0; i < EE; i++){
            float hi = h[i];
            #pragma unroll
            for (int j = 0; j < EE; j++){
                accR[j] = fmaf(hi, sW[1][i][j], accR[j]);
                accZ[j] = fmaf(hi, sW[3][i][j], accZ[j]);
            }
        }

        float r[EE], g[EE];
        #pragma unroll
        for (int j = 0; j < EE; j++){
            r[j] = sigmoidf_fast(accR[j]);
            g[j] = h[j] * sigmoidf_fast(accZ[j]);
        }

        #pragma unroll
        for (int i = 0; i < EE; i++){
            float gi = g[i];
            #pragma unroll
            for (int j = 0; j < EE; j++)
                accH[j] = fmaf(gi, sW[5][i][j], accH[j]);
        }

        #pragma unroll
        for (int j = 0; j < EE; j++){
            float hc = tanhf_fast(accH[j]);
            float Ra = a[j] * r[j];
            h[j] = h[j] + Ra * (hc - h[j]);
        }

        // ---- stage step t+1 into the other buffer ----
        if (t + 1 < TT){
            float* buf = sIn[(t + 1) & 1];
            #pragma unroll
            for (int k = 0; k < 5; k++){
                int e = 4*(tid + NTH*k);
                int row = e / 20, col = e % 20;
                float* d = &buf[row * RSTRIDE + col];
                *(float2*)(d)     = make_float2(f4[k].x, f4[k].y);
                *(float2*)(d + 2) = make_float2(f4[k].z, f4[k].w);
            }
        }
        __syncthreads();
    }

    long b = (long)b0 + tid;
    #pragma unroll
    for (int p = 0; p < 5; p++){
        float2 o; o.x = h[2*p]; o.y = h[2*p+1];
        *(float2*)(out + b*EE + 2*p) = o;
    }
}

extern "C" void kernel_launch(void* const* d_in, const int* in_sizes, int n_in,
                              void* d_out, int out_size)
{
    const float* X   = (const float*)d_in[0];
    const float* Aat = (const float*)d_in[1];
    const float* h0  = (const float*)d_in[2];

    dim3 tg(BB / BTILE, TT / TCH);      // 2048 x 5
    transpose_kernel<<<tg, 256>>>(X, Aat);

    augru_kernel<<<BB / NTH, NTH>>>(
        h0,
        (const float*)d_in[3],  (const float*)d_in[4],  (const float*)d_in[5],
        (const float*)d_in[6],  (const float*)d_in[7],
        (const float*)d_in[8],  (const float*)d_in[9],  (const float*)d_in[10],
        (const float*)d_in[11], (const float*)d_in[12],
        (const float*)d_in[13], (const float*)d_in[14], (const float*)d_in[15],
        (const float*)d_in[16], (const float*)d_in[17],
        (float*)d_out);
}